// round 1
// baseline (speedup 1.0000x reference)
#include <cuda_runtime.h>
#include <math.h>

#define B_ 16
#define S_ 4096
#define H_ 1024
#define C_ 64

// 16 MB scratch for scores / softmax factors: [B][C][S]
__device__ __align__(16) float g_scores[B_ * C_ * S_];

#define FMA2(acc, a2, b2) \
    asm("fma.rn.f32x2 %0, %1, %2, %0;" : "+l"(acc) : "l"(a2), "l"(b2))

#define PACK2(dst, f) \
    asm("mov.b64 %0, {%1, %1};" : "=l"(dst) : "r"(__float_as_uint(f)))

// ---------------------------------------------------------------------------
// K1: scores[b][c][s] = sum_h hidden[b][s][h] * querys[c][h]
// CTA tile: M=C=64, N=128 s-values, K-chunk=32 h. 128 threads, 8m x 4 f32x2-pairs.
// ---------------------------------------------------------------------------
__global__ __launch_bounds__(128) void k1_scores(const float* __restrict__ hidden,
                                                 const float* __restrict__ querys) {
    const int b  = blockIdx.y;
    const int s0 = blockIdx.x * 128;

    __shared__ float As[64 * 36];    // querys tile [c][k], row stride 36 (16B-aligned rows)
    __shared__ float Bs[32 * 130];   // hidden tile transposed [k][s], row stride 130 (8B-aligned rows)

    const int tid = threadIdx.x;
    const int tx = tid & 15;
    const int ty = tid >> 4;

    unsigned long long acc[8][4];
#pragma unroll
    for (int i = 0; i < 8; i++)
#pragma unroll
        for (int j = 0; j < 4; j++) acc[i][j] = 0ULL;

    const float* hbase = hidden + ((size_t)b * S_ + s0) * H_;

    for (int h0 = 0; h0 < H_; h0 += 32) {
        // Load querys tile 64x32 (512 float4, 4 per thread)
#pragma unroll
        for (int t = 0; t < 4; t++) {
            int idx = tid + t * 128;
            int c = idx >> 3;
            int kq = (idx & 7) << 2;
            float4 v = *reinterpret_cast<const float4*>(querys + c * H_ + h0 + kq);
            *reinterpret_cast<float4*>(&As[c * 36 + kq]) = v;
        }
        // Load hidden tile 128x32 and transpose into Bs[k][s] (1024 float4, 8 per thread)
#pragma unroll
        for (int t = 0; t < 8; t++) {
            int idx = tid + t * 128;
            int s = idx >> 3;
            int kq = (idx & 7) << 2;
            float4 v = *reinterpret_cast<const float4*>(hbase + (size_t)s * H_ + h0 + kq);
            Bs[(kq + 0) * 130 + s] = v.x;
            Bs[(kq + 1) * 130 + s] = v.y;
            Bs[(kq + 2) * 130 + s] = v.z;
            Bs[(kq + 3) * 130 + s] = v.w;
        }
        __syncthreads();

#pragma unroll 8
        for (int k = 0; k < 32; k++) {
            unsigned long long a2[8];
#pragma unroll
            for (int i = 0; i < 8; i++) {
                float a = As[(ty * 8 + i) * 36 + k];
                PACK2(a2[i], a);
            }
            unsigned long long b2[4];
#pragma unroll
            for (int j = 0; j < 4; j++) {
                b2[j] = *reinterpret_cast<const unsigned long long*>(
                    &Bs[k * 130 + 2 * (j * 16 + tx)]);
            }
#pragma unroll
            for (int i = 0; i < 8; i++)
#pragma unroll
                for (int j = 0; j < 4; j++) FMA2(acc[i][j], a2[i], b2[j]);
        }
        __syncthreads();
    }

    // scores[b][c][s0 + n], packed pair (n, n+1) per acc
    float* obase = g_scores + (size_t)b * C_ * S_ + s0;
#pragma unroll
    for (int i = 0; i < 8; i++) {
        int c = ty * 8 + i;
#pragma unroll
        for (int j = 0; j < 4; j++) {
            int n = 2 * (j * 16 + tx);
            *reinterpret_cast<unsigned long long*>(obase + (size_t)c * S_ + n) = acc[i][j];
        }
    }
}

// ---------------------------------------------------------------------------
// K2: softmax over s (4096) for each of B*C = 1024 rows, in place in g_scores.
// ---------------------------------------------------------------------------
__global__ __launch_bounds__(256) void k2_softmax() {
    __shared__ float red_max[8];
    __shared__ float red_sum[8];

    float* row = g_scores + (size_t)blockIdx.x * S_;
    const int tid = threadIdx.x;

    float4 v[4];
    float mx = -1e30f;
#pragma unroll
    for (int t = 0; t < 4; t++) {
        v[t] = reinterpret_cast<const float4*>(row)[tid + t * 256];
        mx = fmaxf(mx, fmaxf(fmaxf(v[t].x, v[t].y), fmaxf(v[t].z, v[t].w)));
    }
#pragma unroll
    for (int o = 16; o > 0; o >>= 1) mx = fmaxf(mx, __shfl_xor_sync(0xffffffffu, mx, o));
    if ((tid & 31) == 0) red_max[tid >> 5] = mx;
    __syncthreads();
    mx = red_max[0];
#pragma unroll
    for (int w = 1; w < 8; w++) mx = fmaxf(mx, red_max[w]);

    float s = 0.0f;
#pragma unroll
    for (int t = 0; t < 4; t++) {
        v[t].x = expf(v[t].x - mx);
        v[t].y = expf(v[t].y - mx);
        v[t].z = expf(v[t].z - mx);
        v[t].w = expf(v[t].w - mx);
        s += v[t].x + v[t].y + v[t].z + v[t].w;
    }
#pragma unroll
    for (int o = 16; o > 0; o >>= 1) s += __shfl_xor_sync(0xffffffffu, s, o);
    if ((tid & 31) == 0) red_sum[tid >> 5] = s;
    __syncthreads();
    s = red_sum[0];
#pragma unroll
    for (int w = 1; w < 8; w++) s += red_sum[w];

    const float inv = 1.0f / s;
#pragma unroll
    for (int t = 0; t < 4; t++) {
        v[t].x *= inv; v[t].y *= inv; v[t].z *= inv; v[t].w *= inv;
        reinterpret_cast<float4*>(row)[tid + t * 256] = v[t];
    }
}

// ---------------------------------------------------------------------------
// K3: out[b][c*H + h] = sum_s factor[b][c][s] * hidden[b][s][h]
// CTA tile: M=C=64, N=64 h-values, K-chunk=32 s. 128 threads, 8m x 2 f32x2-pairs.
// ---------------------------------------------------------------------------
__global__ __launch_bounds__(128) void k3_pool(const float* __restrict__ hidden,
                                               float* __restrict__ out) {
    const int b  = blockIdx.y;
    const int h0 = blockIdx.x * 64;

    __shared__ float As[64 * 36];   // factor tile [c][k], row stride 36
    __shared__ float Bs[32 * 64];   // hidden tile [k][n], natural layout

    const int tid = threadIdx.x;
    const int tx = tid & 15;
    const int ty = tid >> 4;

    unsigned long long acc[8][2];
#pragma unroll
    for (int i = 0; i < 8; i++)
#pragma unroll
        for (int j = 0; j < 2; j++) acc[i][j] = 0ULL;

    const float* fbase = g_scores + (size_t)b * C_ * S_;
    const float* hbase = hidden + (size_t)b * S_ * H_ + h0;

    for (int s0 = 0; s0 < S_; s0 += 32) {
        // factor tile 64x32 (512 float4, 4 per thread)
#pragma unroll
        for (int t = 0; t < 4; t++) {
            int idx = tid + t * 128;
            int c = idx >> 3;
            int kq = (idx & 7) << 2;
            float4 v = *reinterpret_cast<const float4*>(fbase + (size_t)c * S_ + s0 + kq);
            *reinterpret_cast<float4*>(&As[c * 36 + kq]) = v;
        }
        // hidden tile 32x64 (512 float4, 4 per thread), natural [k][n]
#pragma unroll
        for (int t = 0; t < 4; t++) {
            int idx = tid + t * 128;
            int k = idx >> 4;
            int nq = (idx & 15) << 2;
            float4 v = *reinterpret_cast<const float4*>(hbase + (size_t)(s0 + k) * H_ + nq);
            *reinterpret_cast<float4*>(&Bs[k * 64 + nq]) = v;
        }
        __syncthreads();

#pragma unroll 8
        for (int k = 0; k < 32; k++) {
            unsigned long long a2[8];
#pragma unroll
            for (int i = 0; i < 8; i++) {
                float a = As[(ty * 8 + i) * 36 + k];
                PACK2(a2[i], a);
            }
            unsigned long long b2[2];
#pragma unroll
            for (int j = 0; j < 2; j++) {
                b2[j] = *reinterpret_cast<const unsigned long long*>(
                    &Bs[k * 64 + 2 * (j * 16 + tx)]);
            }
#pragma unroll
            for (int i = 0; i < 8; i++)
#pragma unroll
                for (int j = 0; j < 2; j++) FMA2(acc[i][j], a2[i], b2[j]);
        }
        __syncthreads();
    }

    float* ob = out + (size_t)b * (C_ * H_) + h0;
#pragma unroll
    for (int i = 0; i < 8; i++) {
        int c = ty * 8 + i;
#pragma unroll
        for (int j = 0; j < 2; j++) {
            int n = 2 * (j * 16 + tx);
            *reinterpret_cast<unsigned long long*>(ob + (size_t)c * H_ + n) = acc[i][j];
        }
    }
}

// ---------------------------------------------------------------------------
extern "C" void kernel_launch(void* const* d_in, const int* in_sizes, int n_in,
                              void* d_out, int out_size) {
    const float* hidden = (const float*)d_in[0];   // [B, S, H] fp32
    const float* querys = (const float*)d_in[1];   // [C, H]    fp32
    float* out = (float*)d_out;                    // [B, C*H]  fp32

    dim3 g1(S_ / 128, B_);
    k1_scores<<<g1, 128>>>(hidden, querys);

    k2_softmax<<<B_ * C_, 256>>>();

    dim3 g3(H_ / 64, B_);
    k3_pool<<<g3, 128>>>(hidden, out);
}

// round 3
// speedup vs baseline: 2.2457x; 2.2457x over previous
#include <cuda_runtime.h>
#include <cuda_bf16.h>
#include <cstdint>
#include <math.h>

#define B_ 16
#define S_ 4096
#define H_ 1024
#define C_ 64

// 16 MB scratch for scores / softmax factors: [B][C][S]
__device__ __align__(16) float g_scores[B_ * C_ * S_];

// ===========================================================================
// Helpers
// ===========================================================================
__device__ __forceinline__ uint32_t smem_u32(const void* p) {
    uint32_t a;
    asm("{ .reg .u64 t; cvta.to.shared.u64 t, %1; cvt.u32.u64 %0, t; }"
        : "=r"(a) : "l"(p));
    return a;
}

// pack (f0 -> low half, f1 -> high half) as bf16x2
__device__ __forceinline__ uint32_t pack_bf2(float f0, float f1) {
    uint32_t r;
    asm("cvt.rn.bf16x2.f32 %0, %2, %1;" : "=r"(r) : "f"(f0), "f"(f1));
    return r;
}

// split float4 into hi-bf16x4 and lo-bf16x4 (lo = x - hi, rounded to bf16)
__device__ __forceinline__ void cvt_split(float4 v, unsigned long long& hh,
                                          unsigned long long& ll) {
    uint32_t h01 = pack_bf2(v.x, v.y);
    uint32_t h23 = pack_bf2(v.z, v.w);
    float l0 = v.x - __uint_as_float(h01 << 16);
    float l1 = v.y - __uint_as_float(h01 & 0xffff0000u);
    float l2 = v.z - __uint_as_float(h23 << 16);
    float l3 = v.w - __uint_as_float(h23 & 0xffff0000u);
    hh = ((unsigned long long)h23 << 32) | h01;
    ll = ((unsigned long long)pack_bf2(l2, l3) << 32) | pack_bf2(l0, l1);
}

__device__ __forceinline__ void st64(uint32_t a, unsigned long long v) {
    asm volatile("st.shared.b64 [%0], %1;" :: "r"(a), "l"(v) : "memory");
}

#define LDSM_X4(r0, r1, r2, r3, a) \
    asm volatile("ldmatrix.sync.aligned.m8n8.x4.shared.b16 {%0,%1,%2,%3}, [%4];" \
                 : "=r"(r0), "=r"(r1), "=r"(r2), "=r"(r3) : "r"(a))

#define LDSM_X4T(r0, r1, r2, r3, a) \
    asm volatile("ldmatrix.sync.aligned.m8n8.x4.trans.shared.b16 {%0,%1,%2,%3}, [%4];" \
                 : "=r"(r0), "=r"(r1), "=r"(r2), "=r"(r3) : "r"(a))

#define MMA_BF16(d, a, b0, b1) \
    asm volatile("mma.sync.aligned.m16n8k16.row.col.f32.bf16.bf16.f32 " \
                 "{%0,%1,%2,%3}, {%4,%5,%6,%7}, {%8,%9}, {%0,%1,%2,%3};" \
                 : "+f"((d)[0]), "+f"((d)[1]), "+f"((d)[2]), "+f"((d)[3]) \
                 : "r"((a)[0]), "r"((a)[1]), "r"((a)[2]), "r"((a)[3]), \
                   "r"(b0), "r"(b1))

// ===========================================================================
// K1: scores[b][c][s] = sum_h hidden[b][s][h] * querys[c][h]
// D[s,c]: M=128 s, N=64 c, K=1024 h (16 chunks of 64).
// A = hidden (row-major, k contig). B = querys[c][h] (n-major) -> plain ldmatrix.
// ===========================================================================
#define K1_STRIDE 144                      // bytes per smem row (72 bf16)
#define K1_A_SZ   (128 * K1_STRIDE)        // 18432
#define K1_B_SZ   (64 * K1_STRIDE)         // 9216
#define K1_BUF    (2 * K1_A_SZ + 2 * K1_B_SZ)  // 55296
#define K1_SMEM   (2 * K1_BUF)             // 110592

__global__ void __launch_bounds__(256, 1) k1_mma(const float* __restrict__ hidden,
                                                 const float* __restrict__ querys) {
    extern __shared__ char smem[];
    const uint32_t sb = smem_u32(smem);
    const int tid = threadIdx.x, lane = tid & 31, wid = tid >> 5;
    const int b = blockIdx.y, s0 = blockIdx.x * 128;
    const int mrow0 = (wid >> 1) * 32, ncol0 = (wid & 1) * 32;
    const uint32_t rowoff = (lane & 7) + ((lane >> 3) & 1) * 8;
    const uint32_t coloff = (lane >> 4) * 8;
    const int g = lane >> 2, tg = lane & 3;

    const float* hbase = hidden + ((size_t)b * S_ + s0) * H_;

    float4 hv[8], qv[4];
    float acc[2][4][4] = {};

    auto LDG = [&](int ch) {
        const int h0 = ch * 64;
#pragma unroll
        for (int t = 0; t < 8; t++) {
            int idx = tid + t * 256, row = idx >> 4, f4 = idx & 15;
            hv[t] = *reinterpret_cast<const float4*>(hbase + (size_t)row * H_ + h0 + f4 * 4);
        }
#pragma unroll
        for (int t = 0; t < 4; t++) {
            int idx = tid + t * 256, row = idx >> 4, f4 = idx & 15;
            qv[t] = *reinterpret_cast<const float4*>(querys + (size_t)row * H_ + h0 + f4 * 4);
        }
    };

    auto STS = [&](int buf) {
        const uint32_t aHi = sb + buf * K1_BUF;
        const uint32_t aLo = aHi + K1_A_SZ;
        const uint32_t bHi = aLo + K1_A_SZ;
        const uint32_t bLo = bHi + K1_B_SZ;
#pragma unroll
        for (int t = 0; t < 8; t++) {
            int idx = tid + t * 256, row = idx >> 4, f4 = idx & 15;
            unsigned long long hh, ll;
            cvt_split(hv[t], hh, ll);
            uint32_t off = row * K1_STRIDE + f4 * 8;
            st64(aHi + off, hh);
            st64(aLo + off, ll);
        }
#pragma unroll
        for (int t = 0; t < 4; t++) {
            int idx = tid + t * 256, row = idx >> 4, f4 = idx & 15;
            unsigned long long hh, ll;
            cvt_split(qv[t], hh, ll);
            uint32_t off = row * K1_STRIDE + f4 * 8;
            st64(bHi + off, hh);
            st64(bLo + off, ll);
        }
    };

    auto COMPUTE = [&](int buf) {
        const uint32_t aHi = sb + buf * K1_BUF;
        const uint32_t aLo = aHi + K1_A_SZ;
        const uint32_t bHi = aLo + K1_A_SZ;
        const uint32_t bLo = bHi + K1_B_SZ;
#pragma unroll
        for (int k16 = 0; k16 < 4; k16++) {
            const uint32_t kb = (k16 * 16 + coloff) * 2;
            uint32_t ah[2][4], al[2][4];
#pragma unroll
            for (int mi = 0; mi < 2; mi++) {
                uint32_t off = (mrow0 + mi * 16 + rowoff) * K1_STRIDE + kb;
                LDSM_X4(ah[mi][0], ah[mi][1], ah[mi][2], ah[mi][3], aHi + off);
                LDSM_X4(al[mi][0], al[mi][1], al[mi][2], al[mi][3], aLo + off);
            }
            uint32_t bh[4][2], bl[4][2];
#pragma unroll
            for (int nh = 0; nh < 2; nh++) {
                uint32_t off = (ncol0 + nh * 16 + rowoff) * K1_STRIDE + kb;
                uint32_t r0, r1, r2, r3;
                LDSM_X4(r0, r1, r2, r3, bHi + off);
                bh[nh * 2][0] = r0; bh[nh * 2][1] = r2;
                bh[nh * 2 + 1][0] = r1; bh[nh * 2 + 1][1] = r3;
                LDSM_X4(r0, r1, r2, r3, bLo + off);
                bl[nh * 2][0] = r0; bl[nh * 2][1] = r2;
                bl[nh * 2 + 1][0] = r1; bl[nh * 2 + 1][1] = r3;
            }
#pragma unroll
            for (int mi = 0; mi < 2; mi++)
#pragma unroll
                for (int ni = 0; ni < 4; ni++) {
                    MMA_BF16(acc[mi][ni], ah[mi], bh[ni][0], bh[ni][1]);
                    MMA_BF16(acc[mi][ni], ah[mi], bl[ni][0], bl[ni][1]);
                    MMA_BF16(acc[mi][ni], al[mi], bh[ni][0], bh[ni][1]);
                }
        }
    };

    LDG(0);
    STS(0);
    __syncthreads();
#pragma unroll 1
    for (int ch = 0; ch < 16; ch++) {
        if (ch < 15) LDG(ch + 1);
        COMPUTE(ch & 1);
        __syncthreads();
        if (ch < 15) {
            STS((ch + 1) & 1);
            __syncthreads();
        }
    }

    // Epilogue: transpose through smem -> coalesced [c][s] stores
    float* T = reinterpret_cast<float*>(smem);  // 64 x 132
#pragma unroll
    for (int mi = 0; mi < 2; mi++)
#pragma unroll
        for (int ni = 0; ni < 4; ni++) {
            int srow = mrow0 + mi * 16 + g;
            int ccol = ncol0 + ni * 8 + tg * 2;
            T[ccol * 132 + srow] = acc[mi][ni][0];
            T[(ccol + 1) * 132 + srow] = acc[mi][ni][1];
            T[ccol * 132 + srow + 8] = acc[mi][ni][2];
            T[(ccol + 1) * 132 + srow + 8] = acc[mi][ni][3];
        }
    __syncthreads();
    float* gs = g_scores + (size_t)b * C_ * S_ + s0;
#pragma unroll
    for (int t = 0; t < 8; t++) {
        int idx = tid + t * 256, row = idx >> 5, f4 = idx & 31;
        float4 v = *reinterpret_cast<const float4*>(&T[row * 132 + f4 * 4]);
        *reinterpret_cast<float4*>(gs + (size_t)row * S_ + f4 * 4) = v;
    }
}

// ===========================================================================
// K2: softmax over s (4096) for each of B*C = 1024 rows, in place.
// ===========================================================================
__global__ __launch_bounds__(256) void k2_softmax() {
    __shared__ float red_max[8];
    __shared__ float red_sum[8];

    float* row = g_scores + (size_t)blockIdx.x * S_;
    const int tid = threadIdx.x;

    float4 v[4];
    float mx = -1e30f;
#pragma unroll
    for (int t = 0; t < 4; t++) {
        v[t] = reinterpret_cast<const float4*>(row)[tid + t * 256];
        mx = fmaxf(mx, fmaxf(fmaxf(v[t].x, v[t].y), fmaxf(v[t].z, v[t].w)));
    }
#pragma unroll
    for (int o = 16; o > 0; o >>= 1) mx = fmaxf(mx, __shfl_xor_sync(0xffffffffu, mx, o));
    if ((tid & 31) == 0) red_max[tid >> 5] = mx;
    __syncthreads();
    mx = red_max[0];
#pragma unroll
    for (int w = 1; w < 8; w++) mx = fmaxf(mx, red_max[w]);

    float s = 0.0f;
#pragma unroll
    for (int t = 0; t < 4; t++) {
        v[t].x = expf(v[t].x - mx);
        v[t].y = expf(v[t].y - mx);
        v[t].z = expf(v[t].z - mx);
        v[t].w = expf(v[t].w - mx);
        s += v[t].x + v[t].y + v[t].z + v[t].w;
    }
#pragma unroll
    for (int o = 16; o > 0; o >>= 1) s += __shfl_xor_sync(0xffffffffu, s, o);
    if ((tid & 31) == 0) red_sum[tid >> 5] = s;
    __syncthreads();
    s = red_sum[0];
#pragma unroll
    for (int w = 1; w < 8; w++) s += red_sum[w];

    const float inv = 1.0f / s;
#pragma unroll
    for (int t = 0; t < 4; t++) {
        v[t].x *= inv; v[t].y *= inv; v[t].z *= inv; v[t].w *= inv;
        reinterpret_cast<float4*>(row)[tid + t * 256] = v[t];
    }
}

// ===========================================================================
// K3: out[b][c*H+h] = sum_s factor[b][c][s] * hidden[b][s][h]
// D[c,h]: M=64 c, N=128 h, K=4096 s (64 chunks of 64).
// A = factor (row-major, k=s contig). B = hidden[s][h] ([k][n]) -> ldmatrix.trans.
// ===========================================================================
#define K3_ASTR 144                        // factor row stride bytes (72 bf16)
#define K3_BSTR 272                        // hidden row stride bytes (136 bf16)
#define K3_A_SZ (64 * K3_ASTR)             // 9216
#define K3_B_SZ (64 * K3_BSTR)             // 17408
#define K3_BUF  (2 * K3_A_SZ + 2 * K3_B_SZ)   // 53248
#define K3_SMEM (2 * K3_BUF)               // 106496

__global__ void __launch_bounds__(256, 1) k3_mma(const float* __restrict__ hidden,
                                                 float* __restrict__ out) {
    extern __shared__ char smem[];
    const uint32_t sb = smem_u32(smem);
    const int tid = threadIdx.x, lane = tid & 31, wid = tid >> 5;
    const int b = blockIdx.y, h0 = blockIdx.x * 128;
    const int mrow0 = (wid >> 2) * 32, ncol0 = (wid & 3) * 32;
    const uint32_t rowoff = (lane & 7) + ((lane >> 3) & 1) * 8;
    const uint32_t coloff = (lane >> 4) * 8;
    const int g = lane >> 2, tg = lane & 3;

    const float* fbase = g_scores + (size_t)b * C_ * S_;
    const float* hbase = hidden + (size_t)b * S_ * H_;

    float4 fv[4], hv[8];
    float acc[2][4][4] = {};

    auto LDG = [&](int ch) {
        const int s0 = ch * 64;
#pragma unroll
        for (int t = 0; t < 4; t++) {
            int idx = tid + t * 256, row = idx >> 4, f4 = idx & 15;
            fv[t] = *reinterpret_cast<const float4*>(fbase + (size_t)row * S_ + s0 + f4 * 4);
        }
#pragma unroll
        for (int t = 0; t < 8; t++) {
            int idx = tid + t * 256, row = idx >> 5, f4 = idx & 31;
            hv[t] = *reinterpret_cast<const float4*>(hbase + (size_t)(s0 + row) * H_ + h0 + f4 * 4);
        }
    };

    auto STS = [&](int buf) {
        const uint32_t aHi = sb + buf * K3_BUF;
        const uint32_t aLo = aHi + K3_A_SZ;
        const uint32_t bHi = aLo + K3_A_SZ;
        const uint32_t bLo = bHi + K3_B_SZ;
#pragma unroll
        for (int t = 0; t < 4; t++) {
            int idx = tid + t * 256, row = idx >> 4, f4 = idx & 15;
            unsigned long long hh, ll;
            cvt_split(fv[t], hh, ll);
            uint32_t off = row * K3_ASTR + f4 * 8;
            st64(aHi + off, hh);
            st64(aLo + off, ll);
        }
#pragma unroll
        for (int t = 0; t < 8; t++) {
            int idx = tid + t * 256, row = idx >> 5, f4 = idx & 31;
            unsigned long long hh, ll;
            cvt_split(hv[t], hh, ll);
            uint32_t off = row * K3_BSTR + f4 * 8;
            st64(bHi + off, hh);
            st64(bLo + off, ll);
        }
    };

    auto COMPUTE = [&](int buf) {
        const uint32_t aHi = sb + buf * K3_BUF;
        const uint32_t aLo = aHi + K3_A_SZ;
        const uint32_t bHi = aLo + K3_A_SZ;
        const uint32_t bLo = bHi + K3_B_SZ;
#pragma unroll
        for (int k16 = 0; k16 < 4; k16++) {
            uint32_t ah[2][4], al[2][4];
#pragma unroll
            for (int mi = 0; mi < 2; mi++) {
                uint32_t off = (mrow0 + mi * 16 + rowoff) * K3_ASTR + (k16 * 16 + coloff) * 2;
                LDSM_X4(ah[mi][0], ah[mi][1], ah[mi][2], ah[mi][3], aHi + off);
                LDSM_X4(al[mi][0], al[mi][1], al[mi][2], al[mi][3], aLo + off);
            }
            uint32_t bh[4][2], bl[4][2];
#pragma unroll
            for (int nh = 0; nh < 2; nh++) {
                // trans: row index = k, col index = n
                uint32_t off = (k16 * 16 + rowoff) * K3_BSTR + (ncol0 + nh * 16 + coloff) * 2;
                uint32_t r0, r1, r2, r3;
                LDSM_X4T(r0, r1, r2, r3, bHi + off);
                bh[nh * 2][0] = r0; bh[nh * 2][1] = r1;
                bh[nh * 2 + 1][0] = r2; bh[nh * 2 + 1][1] = r3;
                LDSM_X4T(r0, r1, r2, r3, bLo + off);
                bl[nh * 2][0] = r0; bl[nh * 2][1] = r1;
                bl[nh * 2 + 1][0] = r2; bl[nh * 2 + 1][1] = r3;
            }
#pragma unroll
            for (int mi = 0; mi < 2; mi++)
#pragma unroll
                for (int ni = 0; ni < 4; ni++) {
                    MMA_BF16(acc[mi][ni], ah[mi], bh[ni][0], bh[ni][1]);
                    MMA_BF16(acc[mi][ni], ah[mi], bl[ni][0], bl[ni][1]);
                    MMA_BF16(acc[mi][ni], al[mi], bh[ni][0], bh[ni][1]);
                }
        }
    };

    LDG(0);
    STS(0);
    __syncthreads();
#pragma unroll 1
    for (int ch = 0; ch < 64; ch++) {
        if (ch < 63) LDG(ch + 1);
        COMPUTE(ch & 1);
        __syncthreads();
        if (ch < 63) {
            STS((ch + 1) & 1);
            __syncthreads();
        }
    }

    // Epilogue: transpose through smem -> coalesced [c][h] stores
    float* T = reinterpret_cast<float*>(smem);  // 64 x 132
#pragma unroll
    for (int mi = 0; mi < 2; mi++)
#pragma unroll
        for (int ni = 0; ni < 4; ni++) {
            int crow = mrow0 + mi * 16 + g;
            int hcol = ncol0 + ni * 8 + tg * 2;
            T[crow * 132 + hcol] = acc[mi][ni][0];
            T[crow * 132 + hcol + 1] = acc[mi][ni][1];
            T[(crow + 8) * 132 + hcol] = acc[mi][ni][2];
            T[(crow + 8) * 132 + hcol + 1] = acc[mi][ni][3];
        }
    __syncthreads();
    float* ob = out + (size_t)b * (C_ * H_) + h0;
#pragma unroll
    for (int t = 0; t < 8; t++) {
        int idx = tid + t * 256, row = idx >> 5, f4 = idx & 31;
        float4 v = *reinterpret_cast<const float4*>(&T[row * 132 + f4 * 4]);
        *reinterpret_cast<float4*>(ob + (size_t)row * H_ + f4 * 4) = v;
    }
}

// ---------------------------------------------------------------------------
extern "C" void kernel_launch(void* const* d_in, const int* in_sizes, int n_in,
                              void* d_out, int out_size) {
    const float* hidden = (const float*)d_in[0];   // [B, S, H] fp32
    const float* querys = (const float*)d_in[1];   // [C, H]    fp32
    float* out = (float*)d_out;                    // [B, C*H]  fp32

    cudaFuncSetAttribute(k1_mma, cudaFuncAttributeMaxDynamicSharedMemorySize, K1_SMEM);
    cudaFuncSetAttribute(k3_mma, cudaFuncAttributeMaxDynamicSharedMemorySize, K3_SMEM);

    dim3 g1(S_ / 128, B_);
    k1_mma<<<g1, 256, K1_SMEM>>>(hidden, querys);

    k2_softmax<<<B_ * C_, 256>>>();

    dim3 g3(H_ / 128, B_);
    k3_mma<<<g3, 256, K3_SMEM>>>(hidden, out);
}